// round 1
// baseline (speedup 1.0000x reference)
#include <cuda_runtime.h>
#include <math_constants.h>

#define BB 4
#define NN 4096
#define DD 256

// Scratch (device globals: allocation-free rule)
__device__ float g_Qt[(size_t)BB*DD*NN];   // (b, d, n)  16 MB
__device__ float g_Kt[(size_t)BB*DD*NN];   // (b, d, n)  16 MB
__device__ float g_V [(size_t)BB*NN*DD];   // (b, n, d)  16 MB
__device__ float g_S [(size_t)BB*NN*NN];   // (b, nq, nk) 268 MB

// ---------------------------------------------------------------------------
// Kernel 1: fused QKV projection.
//   A[m][k] = x[b][k][m]  (x is (B,D,N), so k-major rows are n-contiguous)
//   C = A @ W + bias
//   w==0 -> Qt (d-major), w==1 -> Kt (d-major), w==2 -> V (n,d row-major)
// ---------------------------------------------------------------------------
__global__ __launch_bounds__(256, 2) void proj_kernel(
    const float* __restrict__ x,
    const float* __restrict__ Wq, const float* __restrict__ bq,
    const float* __restrict__ Wk, const float* __restrict__ bk,
    const float* __restrict__ Wv, const float* __restrict__ bv)
{
    __shared__ float As[16][132];
    __shared__ float Bs[16][132];

    const int bz = blockIdx.z;
    const int b  = bz / 3;
    const int w  = bz % 3;
    const float* W    = (w == 0) ? Wq : ((w == 1) ? Wk : Wv);
    const float* bias = (w == 0) ? bq : ((w == 1) ? bk : bv);

    const int m0 = blockIdx.x * 128;   // n-range
    const int d0 = blockIdx.y * 128;   // output-d range
    const int tid = threadIdx.x;
    const int tx = tid & 15, ty = tid >> 4;

    const float* Abase = x + (size_t)b * DD * NN;  // A[k][m] = Abase[k*NN + m]

    float acc[8][8] = {};
    float4 pa[2], pb[2];

    // prefetch chunk 0
    #pragma unroll
    for (int u = 0; u < 2; ++u) {
        int idx = tid + u * 256;
        int kl = idx >> 5, m4 = (idx & 31) << 2;
        pa[u] = *(const float4*)(Abase + (size_t)kl * NN + m0 + m4);
        pb[u] = *(const float4*)(W     + (size_t)kl * DD + d0 + m4);
    }

    for (int kc = 0; kc < DD; kc += 16) {
        #pragma unroll
        for (int u = 0; u < 2; ++u) {
            int idx = tid + u * 256;
            int kl = idx >> 5, m4 = (idx & 31) << 2;
            *(float4*)&As[kl][m4] = pa[u];
            *(float4*)&Bs[kl][m4] = pb[u];
        }
        __syncthreads();
        if (kc + 16 < DD) {
            int kn = kc + 16;
            #pragma unroll
            for (int u = 0; u < 2; ++u) {
                int idx = tid + u * 256;
                int kl = idx >> 5, m4 = (idx & 31) << 2;
                pa[u] = *(const float4*)(Abase + (size_t)(kn + kl) * NN + m0 + m4);
                pb[u] = *(const float4*)(W     + (size_t)(kn + kl) * DD + d0 + m4);
            }
        }
        #pragma unroll
        for (int kk = 0; kk < 16; ++kk) {
            float a[8], bv2[8];
            *(float4*)&a[0]   = *(float4*)&As[kk][ty * 8];
            *(float4*)&a[4]   = *(float4*)&As[kk][ty * 8 + 4];
            *(float4*)&bv2[0] = *(float4*)&Bs[kk][tx * 8];
            *(float4*)&bv2[4] = *(float4*)&Bs[kk][tx * 8 + 4];
            #pragma unroll
            for (int i = 0; i < 8; ++i)
                #pragma unroll
                for (int j = 0; j < 8; ++j)
                    acc[i][j] += a[i] * bv2[j];
        }
        __syncthreads();
    }

    if (w < 2) {
        // transposed epilogue: Out[d][n]
        float* Out = ((w == 0) ? g_Qt : g_Kt) + (size_t)b * DD * NN;
        #pragma unroll
        for (int j = 0; j < 8; ++j) {
            int d = d0 + tx * 8 + j;
            float bbv = bias[d];
            float4 v0 = make_float4(acc[0][j] + bbv, acc[1][j] + bbv,
                                    acc[2][j] + bbv, acc[3][j] + bbv);
            float4 v1 = make_float4(acc[4][j] + bbv, acc[5][j] + bbv,
                                    acc[6][j] + bbv, acc[7][j] + bbv);
            *(float4*)(Out + (size_t)d * NN + m0 + ty * 8)     = v0;
            *(float4*)(Out + (size_t)d * NN + m0 + ty * 8 + 4) = v1;
        }
    } else {
        // row-major epilogue: V[n][d]
        float* Out = g_V + (size_t)b * NN * DD;
        #pragma unroll
        for (int i = 0; i < 8; ++i) {
            int n = m0 + ty * 8 + i;
            int d = d0 + tx * 8;
            float4 v0 = make_float4(acc[i][0] + bias[d + 0], acc[i][1] + bias[d + 1],
                                    acc[i][2] + bias[d + 2], acc[i][3] + bias[d + 3]);
            float4 v1 = make_float4(acc[i][4] + bias[d + 4], acc[i][5] + bias[d + 5],
                                    acc[i][6] + bias[d + 6], acc[i][7] + bias[d + 7]);
            *(float4*)(Out + (size_t)n * DD + d)     = v0;
            *(float4*)(Out + (size_t)n * DD + d + 4) = v1;
        }
    }
}

// ---------------------------------------------------------------------------
// Kernel 2: S[b][m][j] = sum_d Qt[b][d][m] * Kt[b][d][j]
// Both operands d-major -> straight coalesced loads into [k][128] smem tiles.
// ---------------------------------------------------------------------------
__global__ __launch_bounds__(256, 2) void qk_kernel()
{
    __shared__ float As[16][132];
    __shared__ float Bs[16][132];

    const int b  = blockIdx.z;
    const int m0 = blockIdx.y * 128;
    const int j0 = blockIdx.x * 128;
    const int tid = threadIdx.x;
    const int tx = tid & 15, ty = tid >> 4;

    const float* Qb = g_Qt + (size_t)b * DD * NN;
    const float* Kb = g_Kt + (size_t)b * DD * NN;

    float acc[8][8] = {};
    float4 pa[2], pb[2];

    #pragma unroll
    for (int u = 0; u < 2; ++u) {
        int idx = tid + u * 256;
        int kl = idx >> 5, m4 = (idx & 31) << 2;
        pa[u] = *(const float4*)(Qb + (size_t)kl * NN + m0 + m4);
        pb[u] = *(const float4*)(Kb + (size_t)kl * NN + j0 + m4);
    }

    for (int kc = 0; kc < DD; kc += 16) {
        #pragma unroll
        for (int u = 0; u < 2; ++u) {
            int idx = tid + u * 256;
            int kl = idx >> 5, m4 = (idx & 31) << 2;
            *(float4*)&As[kl][m4] = pa[u];
            *(float4*)&Bs[kl][m4] = pb[u];
        }
        __syncthreads();
        if (kc + 16 < DD) {
            int kn = kc + 16;
            #pragma unroll
            for (int u = 0; u < 2; ++u) {
                int idx = tid + u * 256;
                int kl = idx >> 5, m4 = (idx & 31) << 2;
                pa[u] = *(const float4*)(Qb + (size_t)(kn + kl) * NN + m0 + m4);
                pb[u] = *(const float4*)(Kb + (size_t)(kn + kl) * NN + j0 + m4);
            }
        }
        #pragma unroll
        for (int kk = 0; kk < 16; ++kk) {
            float a[8], bv2[8];
            *(float4*)&a[0]   = *(float4*)&As[kk][ty * 8];
            *(float4*)&a[4]   = *(float4*)&As[kk][ty * 8 + 4];
            *(float4*)&bv2[0] = *(float4*)&Bs[kk][tx * 8];
            *(float4*)&bv2[4] = *(float4*)&Bs[kk][tx * 8 + 4];
            #pragma unroll
            for (int i = 0; i < 8; ++i)
                #pragma unroll
                for (int j = 0; j < 8; ++j)
                    acc[i][j] += a[i] * bv2[j];
        }
        __syncthreads();
    }

    #pragma unroll
    for (int i = 0; i < 8; ++i) {
        float* Srow = g_S + ((size_t)b * NN + m0 + ty * 8 + i) * NN + j0 + tx * 8;
        *(float4*)(Srow)     = make_float4(acc[i][0], acc[i][1], acc[i][2], acc[i][3]);
        *(float4*)(Srow + 4) = make_float4(acc[i][4], acc[i][5], acc[i][6], acc[i][7]);
    }
}

// ---------------------------------------------------------------------------
// Kernel 3: row softmax over g_S, in place. One block per row (4096 floats).
// ---------------------------------------------------------------------------
__inline__ __device__ float warpMax(float v) {
    #pragma unroll
    for (int o = 16; o; o >>= 1) v = fmaxf(v, __shfl_xor_sync(0xffffffffu, v, o));
    return v;
}
__inline__ __device__ float warpSum(float v) {
    #pragma unroll
    for (int o = 16; o; o >>= 1) v += __shfl_xor_sync(0xffffffffu, v, o);
    return v;
}

__global__ __launch_bounds__(256) void softmax_kernel()
{
    __shared__ float red[8];
    const size_t row = blockIdx.x;
    float* p = g_S + row * (size_t)NN;
    const int tid = threadIdx.x;
    const int lane = tid & 31, wid = tid >> 5;

    float4 v[4];
    float m = -CUDART_INF_F;
    #pragma unroll
    for (int u = 0; u < 4; ++u) {
        v[u] = *(float4*)(p + (size_t)(tid + u * 256) * 4);
        m = fmaxf(m, fmaxf(fmaxf(v[u].x, v[u].y), fmaxf(v[u].z, v[u].w)));
    }
    m = warpMax(m);
    if (lane == 0) red[wid] = m;
    __syncthreads();
    float bm = red[0];
    #pragma unroll
    for (int i = 1; i < 8; ++i) bm = fmaxf(bm, red[i]);
    __syncthreads();

    float s = 0.f;
    #pragma unroll
    for (int u = 0; u < 4; ++u) {
        v[u].x = __expf(v[u].x - bm);
        v[u].y = __expf(v[u].y - bm);
        v[u].z = __expf(v[u].z - bm);
        v[u].w = __expf(v[u].w - bm);
        s += v[u].x + v[u].y + v[u].z + v[u].w;
    }
    s = warpSum(s);
    if (lane == 0) red[wid] = s;
    __syncthreads();
    float tot = 0.f;
    #pragma unroll
    for (int i = 0; i < 8; ++i) tot += red[i];
    float inv = 1.0f / tot;

    #pragma unroll
    for (int u = 0; u < 4; ++u) {
        v[u].x *= inv; v[u].y *= inv; v[u].z *= inv; v[u].w *= inv;
        *(float4*)(p + (size_t)(tid + u * 256) * 4) = v[u];
    }
}

// ---------------------------------------------------------------------------
// Kernel 4: O = P @ V.  P = g_S (m x 4096), V (4096 x 256).
// Output written directly to d_out in (B, D, N) layout (transposed epilogue).
// ---------------------------------------------------------------------------
__global__ __launch_bounds__(256, 2) void av_kernel(float* __restrict__ out)
{
    __shared__ float As[16][132];
    __shared__ float Bs[16][132];

    const int b  = blockIdx.z;
    const int m0 = blockIdx.y * 128;   // query rows
    const int d0 = blockIdx.x * 128;   // output d
    const int tid = threadIdx.x;
    const int tx = tid & 15, ty = tid >> 4;

    const float* Pb = g_S + (size_t)b * NN * NN;  // [m][key]
    const float* Vb = g_V + (size_t)b * NN * DD;  // [key][d]

    float acc[8][8] = {};
    float4 pa[2], pb[2];

    // prefetch chunk 0
    #pragma unroll
    for (int u = 0; u < 2; ++u) {
        int idxA = tid + u * 256;
        int ml = idxA >> 2, c4 = (idxA & 3) << 2;
        pa[u] = *(const float4*)(Pb + (size_t)(m0 + ml) * NN + c4);
        int kl = idxA >> 5, d4 = (idxA & 31) << 2;
        pb[u] = *(const float4*)(Vb + (size_t)kl * DD + d0 + d4);
    }

    for (int kc = 0; kc < NN; kc += 16) {
        #pragma unroll
        for (int u = 0; u < 2; ++u) {
            int idxA = tid + u * 256;
            int ml = idxA >> 2, c4 = (idxA & 3) << 2;
            As[c4 + 0][ml] = pa[u].x;   // transpose-scatter P tile to [k][m]
            As[c4 + 1][ml] = pa[u].y;
            As[c4 + 2][ml] = pa[u].z;
            As[c4 + 3][ml] = pa[u].w;
            int kl = idxA >> 5, d4 = (idxA & 31) << 2;
            *(float4*)&Bs[kl][d4] = pb[u];
        }
        __syncthreads();
        if (kc + 16 < NN) {
            int kn = kc + 16;
            #pragma unroll
            for (int u = 0; u < 2; ++u) {
                int idxA = tid + u * 256;
                int ml = idxA >> 2, c4 = (idxA & 3) << 2;
                pa[u] = *(const float4*)(Pb + (size_t)(m0 + ml) * NN + kn + c4);
                int kl = idxA >> 5, d4 = (idxA & 31) << 2;
                pb[u] = *(const float4*)(Vb + (size_t)(kn + kl) * DD + d0 + d4);
            }
        }
        #pragma unroll
        for (int kk = 0; kk < 16; ++kk) {
            float a[8], bv2[8];
            *(float4*)&a[0]   = *(float4*)&As[kk][ty * 8];
            *(float4*)&a[4]   = *(float4*)&As[kk][ty * 8 + 4];
            *(float4*)&bv2[0] = *(float4*)&Bs[kk][tx * 8];
            *(float4*)&bv2[4] = *(float4*)&Bs[kk][tx * 8 + 4];
            #pragma unroll
            for (int i = 0; i < 8; ++i)
                #pragma unroll
                for (int j = 0; j < 8; ++j)
                    acc[i][j] += a[i] * bv2[j];
        }
        __syncthreads();
    }

    // output (B, D, N): out[b][d][n]
    float* Ob = out + (size_t)b * DD * NN;
    #pragma unroll
    for (int j = 0; j < 8; ++j) {
        int d = d0 + tx * 8 + j;
        float4 v0 = make_float4(acc[0][j], acc[1][j], acc[2][j], acc[3][j]);
        float4 v1 = make_float4(acc[4][j], acc[5][j], acc[6][j], acc[7][j]);
        *(float4*)(Ob + (size_t)d * NN + m0 + ty * 8)     = v0;
        *(float4*)(Ob + (size_t)d * NN + m0 + ty * 8 + 4) = v1;
    }
}

// ---------------------------------------------------------------------------
extern "C" void kernel_launch(void* const* d_in, const int* in_sizes, int n_in,
                              void* d_out, int out_size)
{
    const float* x  = (const float*)d_in[0];
    const float* Wq = (const float*)d_in[1];
    const float* bq = (const float*)d_in[2];
    const float* Wk = (const float*)d_in[3];
    const float* bk = (const float*)d_in[4];
    const float* Wv = (const float*)d_in[5];
    const float* bv = (const float*)d_in[6];
    float* out = (float*)d_out;

    proj_kernel<<<dim3(NN / 128, DD / 128, BB * 3), 256>>>(x, Wq, bq, Wk, bk, Wv, bv);
    qk_kernel<<<dim3(NN / 128, NN / 128, BB), 256>>>();
    softmax_kernel<<<BB * NN, 256>>>();
    av_kernel<<<dim3(DD / 128, NN / 128, BB), 256>>>(out);
}